// round 5
// baseline (speedup 1.0000x reference)
#include <cuda_runtime.h>
#include <math_constants.h>

// Per-cluster expanded quadratic in log2 domain, shifted by the global max:
//   t2_j(x) = F_j + A_j*x0^2 + B_j*x1^2 + C_j*x0*x1 + D_j*x0 + E_j*x1
// Coeffs absorb log2(e); F absorbs -mx2 (mx2 = max_j log2-scaled logw_j).
// Packed 2 clusters per 3 float4: [A0,B0,C0,D0] [E0,F0,A1,B1] [C1,D1,E1,F1]
#define MAX_M 1024
#define NPAIR (MAX_M / 2)
__device__ __align__(16) float4 g_coef[NPAIR * 3];  // 24 KB
__device__ float g_mx2;

// ---------------------------------------------------------------------------
// Prep kernel: one block of 1024 threads.
// ---------------------------------------------------------------------------
__global__ void gmm_prep_kernel(const float* __restrict__ mu,
                                const float* __restrict__ A,
                                const float* __restrict__ w,
                                int M) {
    __shared__ float red[1024];
    int j = threadIdx.x;

    float wj = (j < M) ? w[j] : -CUDART_INF_F;

    red[j] = wj;
    __syncthreads();
    for (int s = 512; s > 0; s >>= 1) {
        if (j < s) red[j] = fmaxf(red[j], red[j + s]);
        __syncthreads();
    }
    float wmax = red[0];
    __syncthreads();

    red[j] = (j < M) ? __expf(wj - wmax) : 0.0f;
    __syncthreads();
    for (int s = 512; s > 0; s >>= 1) {
        if (j < s) red[j] += red[j + s];
        __syncthreads();
    }
    float lse_w = wmax + __logf(red[0]);
    __syncthreads();

    float g00 = 0.f, g01 = 0.f, g11 = 0.f, logw = -CUDART_INF_F;
    float m0 = 0.f, m1 = 0.f;
    if (j < M) {
        float a00 = A[j * 4 + 0];
        float a01 = A[j * 4 + 1];
        float a10 = A[j * 4 + 2];
        float a11 = A[j * 4 + 3];
        g00 = 0.5f * (a00 * a00 + a01 * a01);
        g01 = 0.5f * (a00 * a10 + a01 * a11);
        g11 = 0.5f * (a10 * a10 + a11 * a11);
        float det = g00 * g11 - g01 * g01;
        logw = (wj - lse_w) + 0.5f * __logf(det);
        m0 = mu[j * 2 + 0];
        m1 = mu[j * 2 + 1];
    }

    const float L = 1.4426950408889634f;  // log2(e)
    red[j] = L * logw;
    __syncthreads();
    for (int s = 512; s > 0; s >>= 1) {
        if (j < s) red[j] = fmaxf(red[j], red[j + s]);
        __syncthreads();
    }
    float mx2 = red[0];
    if (j == 0) g_mx2 = mx2;

    if (j < M) {
        float cA = -L * g00;
        float cB = -L * g11;
        float cC = -L * 2.0f * g01;
        float cD =  L * 2.0f * (g00 * m0 + g01 * m1);
        float cE =  L * 2.0f * (g11 * m1 + g01 * m0);
        float cF =  L * (logw - (g00 * m0 * m0 + 2.0f * g01 * m0 * m1 + g11 * m1 * m1))
                    - mx2;

        float* gp = (float*)g_coef;
        int p = j >> 1, h = j & 1;
        int base = p * 12 + h * 6;
        gp[base + 0] = cA;
        gp[base + 1] = cB;
        gp[base + 2] = cC;
        gp[base + 3] = cD;
        gp[base + 4] = cE;
        gp[base + 5] = cF;
    }
}

__device__ __forceinline__ float ex2f(float x) {
    float r;
    asm("ex2.approx.ftz.f32 %0, %1;" : "=f"(r) : "f"(x));
    return r;
}

// Evaluate one cluster's quadratic given its 6 coeffs against one sample.
__device__ __forceinline__ float qeval(float cA, float cB, float cC,
                                       float cD, float cE, float cF,
                                       float x0, float x1,
                                       float x00, float x11, float x01) {
    float t = fmaf(cE, x1, cF);
    t = fmaf(cD, x0,  t);
    t = fmaf(cC, x01, t);
    t = fmaf(cB, x11, t);
    t = fmaf(cA, x00, t);
    return t;
}

// ---------------------------------------------------------------------------
// Main kernel: S=4 samples per thread. Coefficient smem reads amortized 4x.
// 128 CTAs x 128 threads -> one CTA per SM, single balanced wave.
// ---------------------------------------------------------------------------
#define S 4
__global__ __launch_bounds__(128) void gmm_ll_kernel(
    const float* __restrict__ sample,
    float* __restrict__ out,
    int N, int M) {
    __shared__ __align__(16) float4 sc[NPAIR * 3];

    for (int k = threadIdx.x; k < (M >> 1) * 3; k += blockDim.x)
        sc[k] = g_coef[k];
    __syncthreads();

    int base = (blockIdx.x * blockDim.x + threadIdx.x) * S;
    if (base >= N) return;

    // Load 4 samples (32 bytes) via two float4 loads.
    const float4* sp4 = (const float4*)(sample + 2 * base);
    float4 sA = sp4[0];   // x0[0] x1[0] x0[1] x1[1]
    float4 sB = sp4[1];   // x0[2] x1[2] x0[3] x1[3]

    float x0[S]  = { sA.x, sA.z, sB.x, sB.z };
    float x1[S]  = { sA.y, sA.w, sB.y, sB.w };
    float x00[S], x11[S], x01[S];
    #pragma unroll
    for (int s = 0; s < S; s++) {
        x00[s] = x0[s] * x0[s];
        x11[s] = x1[s] * x1[s];
        x01[s] = x0[s] * x1[s];
    }

    float acc0[S], acc1[S];
    #pragma unroll
    for (int s = 0; s < S; s++) { acc0[s] = 0.0f; acc1[s] = 0.0f; }

    const int npair = M >> 1;
    #pragma unroll 2
    for (int p = 0; p < npair; p++) {
        float4 v0 = sc[3 * p + 0];  // A0 B0 C0 D0
        float4 v1 = sc[3 * p + 1];  // E0 F0 A1 B1
        float4 v2 = sc[3 * p + 2];  // C1 D1 E1 F1

        #pragma unroll
        for (int s = 0; s < S; s++) {
            float t0 = qeval(v0.x, v0.y, v0.z, v0.w, v1.x, v1.y,
                             x0[s], x1[s], x00[s], x11[s], x01[s]);
            float t1 = qeval(v1.z, v1.w, v2.x, v2.y, v2.z, v2.w,
                             x0[s], x1[s], x00[s], x11[s], x01[s]);
            acc0[s] += ex2f(t0);
            acc1[s] += ex2f(t1);
        }
    }

    float mx2 = g_mx2;
    float4 res;
    res.x = (mx2 + __log2f(acc0[0] + acc1[0])) * 0.6931471805599453f;
    res.y = (mx2 + __log2f(acc0[1] + acc1[1])) * 0.6931471805599453f;
    res.z = (mx2 + __log2f(acc0[2] + acc1[2])) * 0.6931471805599453f;
    res.w = (mx2 + __log2f(acc0[3] + acc1[3])) * 0.6931471805599453f;
    *(float4*)(out + base) = res;
}

// ---------------------------------------------------------------------------
// Inputs (metadata order): sample [N,2] f32, mu [M,2] f32, A [M,2,2] f32,
// w [M,1] f32. Output: [N,1] f32.
// ---------------------------------------------------------------------------
extern "C" void kernel_launch(void* const* d_in, const int* in_sizes, int n_in,
                              void* d_out, int out_size) {
    const float* sample = (const float*)d_in[0];
    const float* mu     = (const float*)d_in[1];
    const float* A      = (const float*)d_in[2];
    const float* w      = (const float*)d_in[3];
    float* out = (float*)d_out;

    int N = in_sizes[0] / 2;
    int M = in_sizes[3];

    gmm_prep_kernel<<<1, 1024>>>(mu, A, w, M);

    int threads = 128;
    int blocks = (N / S + threads - 1) / threads;   // N=65536 -> 128 CTAs
    gmm_ll_kernel<<<blocks, threads>>>(sample, out, N, M);
}

// round 6
// speedup vs baseline: 1.2599x; 1.2599x over previous
#include <cuda_runtime.h>
#include <math_constants.h>

// Per-cluster expanded quadratic in log2 domain, shifted by the global max:
//   t2_j(x) = F_j + A_j*x0^2 + B_j*x1^2 + C_j*x0*x1 + D_j*x0 + E_j*x1
// Coeffs absorb log2(e); F absorbs -mx2 (mx2 = max_j log2-scaled logw_j).
// Packed 2 clusters per 3 float4: [A0,B0,C0,D0] [E0,F0,A1,B1] [C1,D1,E1,F1]
#define MAX_M 1024
#define NPAIR (MAX_M / 2)
__device__ __align__(16) float4 g_coef[NPAIR * 3];  // 24 KB
__device__ float g_mx2;

// ---------------------------------------------------------------------------
// Prep kernel: one block of 1024 threads.
// ---------------------------------------------------------------------------
__global__ void gmm_prep_kernel(const float* __restrict__ mu,
                                const float* __restrict__ A,
                                const float* __restrict__ w,
                                int M) {
    __shared__ float red[1024];
    int j = threadIdx.x;

    float wj = (j < M) ? w[j] : -CUDART_INF_F;

    red[j] = wj;
    __syncthreads();
    for (int s = 512; s > 0; s >>= 1) {
        if (j < s) red[j] = fmaxf(red[j], red[j + s]);
        __syncthreads();
    }
    float wmax = red[0];
    __syncthreads();

    red[j] = (j < M) ? __expf(wj - wmax) : 0.0f;
    __syncthreads();
    for (int s = 512; s > 0; s >>= 1) {
        if (j < s) red[j] += red[j + s];
        __syncthreads();
    }
    float lse_w = wmax + __logf(red[0]);
    __syncthreads();

    float g00 = 0.f, g01 = 0.f, g11 = 0.f, logw = -CUDART_INF_F;
    float m0 = 0.f, m1 = 0.f;
    if (j < M) {
        float a00 = A[j * 4 + 0];
        float a01 = A[j * 4 + 1];
        float a10 = A[j * 4 + 2];
        float a11 = A[j * 4 + 3];
        g00 = 0.5f * (a00 * a00 + a01 * a01);
        g01 = 0.5f * (a00 * a10 + a01 * a11);
        g11 = 0.5f * (a10 * a10 + a11 * a11);
        float det = g00 * g11 - g01 * g01;
        logw = (wj - lse_w) + 0.5f * __logf(det);
        m0 = mu[j * 2 + 0];
        m1 = mu[j * 2 + 1];
    }

    const float L = 1.4426950408889634f;  // log2(e)
    red[j] = L * logw;
    __syncthreads();
    for (int s = 512; s > 0; s >>= 1) {
        if (j < s) red[j] = fmaxf(red[j], red[j + s]);
        __syncthreads();
    }
    float mx2 = red[0];
    if (j == 0) g_mx2 = mx2;

    if (j < M) {
        float cA = -L * g00;
        float cB = -L * g11;
        float cC = -L * 2.0f * g01;
        float cD =  L * 2.0f * (g00 * m0 + g01 * m1);
        float cE =  L * 2.0f * (g11 * m1 + g01 * m0);
        float cF =  L * (logw - (g00 * m0 * m0 + 2.0f * g01 * m0 * m1 + g11 * m1 * m1))
                    - mx2;

        float* gp = (float*)g_coef;
        int p = j >> 1, h = j & 1;
        int base = p * 12 + h * 6;
        gp[base + 0] = cA;
        gp[base + 1] = cB;
        gp[base + 2] = cC;
        gp[base + 3] = cD;
        gp[base + 4] = cE;
        gp[base + 5] = cF;
    }
}

__device__ __forceinline__ float ex2f(float x) {
    float r;
    asm("ex2.approx.ftz.f32 %0, %1;" : "=f"(r) : "f"(x));
    return r;
}

__device__ __forceinline__ float qeval(float cA, float cB, float cC,
                                       float cD, float cE, float cF,
                                       float x0, float x1,
                                       float x00, float x11, float x01) {
    float t = fmaf(cE, x1, cF);
    t = fmaf(cD, x0,  t);
    t = fmaf(cC, x01, t);
    t = fmaf(cB, x11, t);
    t = fmaf(cA, x00, t);
    return t;
}

// ---------------------------------------------------------------------------
// Main kernel: 256 threads/CTA, 128 CTAs (one per SM, single wave).
// S=4 samples per thread-slot; the CTA's two 128-thread halves each cover
// half the cluster pairs over the SAME 512 samples; partial sums combined
// through shared memory. S=4 keeps smem-crossbar traffic at ~1/4, the M-split
// restores 2 warps/SMSP for latency hiding.
// ---------------------------------------------------------------------------
#define S 4
__global__ __launch_bounds__(256) void gmm_ll_kernel(
    const float* __restrict__ sample,
    float* __restrict__ out,
    int N, int M) {
    __shared__ __align__(16) float4 sc[NPAIR * 3];   // 24 KB
    __shared__ __align__(16) float4 s_part[128];     // 2 KB partial sums

    const int npair = M >> 1;
    for (int k = threadIdx.x; k < npair * 3; k += blockDim.x)
        sc[k] = g_coef[k];
    __syncthreads();

    const int half = threadIdx.x >> 7;        // 0 or 1: which half of clusters
    const int lane = threadIdx.x & 127;       // sample slot within CTA
    const int base = (blockIdx.x * 128 + lane) * S;

    // Load 4 samples (32 B) via two float4 loads (both halves load the same).
    const float4* sp4 = (const float4*)(sample + 2 * base);
    float4 sA = sp4[0];
    float4 sB = sp4[1];

    float x0[S]  = { sA.x, sA.z, sB.x, sB.z };
    float x1[S]  = { sA.y, sA.w, sB.y, sB.w };
    float x00[S], x11[S], x01[S];
    #pragma unroll
    for (int s = 0; s < S; s++) {
        x00[s] = x0[s] * x0[s];
        x11[s] = x1[s] * x1[s];
        x01[s] = x0[s] * x1[s];
    }

    float acc0[S], acc1[S];
    #pragma unroll
    for (int s = 0; s < S; s++) { acc0[s] = 0.0f; acc1[s] = 0.0f; }

    const int half_np = npair >> 1;           // 256 pairs per half
    const int p_beg = half * half_np;
    const int p_end = p_beg + half_np;

    #pragma unroll 2
    for (int p = p_beg; p < p_end; p++) {
        float4 v0 = sc[3 * p + 0];  // A0 B0 C0 D0
        float4 v1 = sc[3 * p + 1];  // E0 F0 A1 B1
        float4 v2 = sc[3 * p + 2];  // C1 D1 E1 F1

        #pragma unroll
        for (int s = 0; s < S; s++) {
            float t0 = qeval(v0.x, v0.y, v0.z, v0.w, v1.x, v1.y,
                             x0[s], x1[s], x00[s], x11[s], x01[s]);
            float t1 = qeval(v1.z, v1.w, v2.x, v2.y, v2.z, v2.w,
                             x0[s], x1[s], x00[s], x11[s], x01[s]);
            acc0[s] += ex2f(t0);
            acc1[s] += ex2f(t1);
        }
    }

    float4 mysum;
    mysum.x = acc0[0] + acc1[0];
    mysum.y = acc0[1] + acc1[1];
    mysum.z = acc0[2] + acc1[2];
    mysum.w = acc0[3] + acc1[3];

    if (half == 1) s_part[lane] = mysum;
    __syncthreads();

    if (half == 0) {
        float4 other = s_part[lane];
        float mx2 = g_mx2;
        const float LN2 = 0.6931471805599453f;
        float4 res;
        res.x = (mx2 + __log2f(mysum.x + other.x)) * LN2;
        res.y = (mx2 + __log2f(mysum.y + other.y)) * LN2;
        res.z = (mx2 + __log2f(mysum.z + other.z)) * LN2;
        res.w = (mx2 + __log2f(mysum.w + other.w)) * LN2;
        *(float4*)(out + base) = res;
    }
}

// ---------------------------------------------------------------------------
// Inputs (metadata order): sample [N,2] f32, mu [M,2] f32, A [M,2,2] f32,
// w [M,1] f32. Output: [N,1] f32.
// ---------------------------------------------------------------------------
extern "C" void kernel_launch(void* const* d_in, const int* in_sizes, int n_in,
                              void* d_out, int out_size) {
    const float* sample = (const float*)d_in[0];
    const float* mu     = (const float*)d_in[1];
    const float* A      = (const float*)d_in[2];
    const float* w      = (const float*)d_in[3];
    float* out = (float*)d_out;

    int N = in_sizes[0] / 2;
    int M = in_sizes[3];

    gmm_prep_kernel<<<1, 1024>>>(mu, A, w, M);

    int samples_per_cta = 128 * S;                       // 512
    int blocks = (N + samples_per_cta - 1) / samples_per_cta;  // 128
    gmm_ll_kernel<<<blocks, 256>>>(sample, out, N, M);
}

// round 9
// speedup vs baseline: 1.3162x; 1.0447x over previous
#include <cuda_runtime.h>
#include <math_constants.h>

// Per-cluster expanded quadratic in log2 domain, shifted by the global max:
//   t2_j(x) = F_j + A_j*x0^2 + B_j*x1^2 + C_j*x0*x1 + D_j*x0 + E_j*x1
// Coeffs absorb log2(e); F absorbs -mx2 (mx2 = max_j log2-scaled logw_j).
// Packed 2 clusters per 3 float4: [A0,B0,C0,D0] [E0,F0,A1,B1] [C1,D1,E1,F1]
#define MAX_M 1024
#define NPAIR (MAX_M / 2)
__device__ __align__(16) float4 g_coef[NPAIR * 3];  // 24 KB
__device__ float g_mx2;

// ---------------------------------------------------------------------------
// Prep kernel: one block of 1024 threads.
// ---------------------------------------------------------------------------
__global__ void gmm_prep_kernel(const float* __restrict__ mu,
                                const float* __restrict__ A,
                                const float* __restrict__ w,
                                int M) {
    __shared__ float red[1024];
    int j = threadIdx.x;

    float wj = (j < M) ? w[j] : -CUDART_INF_F;

    red[j] = wj;
    __syncthreads();
    for (int s = 512; s > 0; s >>= 1) {
        if (j < s) red[j] = fmaxf(red[j], red[j + s]);
        __syncthreads();
    }
    float wmax = red[0];
    __syncthreads();

    red[j] = (j < M) ? __expf(wj - wmax) : 0.0f;
    __syncthreads();
    for (int s = 512; s > 0; s >>= 1) {
        if (j < s) red[j] += red[j + s];
        __syncthreads();
    }
    float lse_w = wmax + __logf(red[0]);
    __syncthreads();

    float g00 = 0.f, g01 = 0.f, g11 = 0.f, logw = -CUDART_INF_F;
    float m0 = 0.f, m1 = 0.f;
    if (j < M) {
        float a00 = A[j * 4 + 0];
        float a01 = A[j * 4 + 1];
        float a10 = A[j * 4 + 2];
        float a11 = A[j * 4 + 3];
        g00 = 0.5f * (a00 * a00 + a01 * a01);
        g01 = 0.5f * (a00 * a10 + a01 * a11);
        g11 = 0.5f * (a10 * a10 + a11 * a11);
        float det = g00 * g11 - g01 * g01;
        logw = (wj - lse_w) + 0.5f * __logf(det);
        m0 = mu[j * 2 + 0];
        m1 = mu[j * 2 + 1];
    }

    const float L = 1.4426950408889634f;  // log2(e)
    red[j] = L * logw;
    __syncthreads();
    for (int s = 512; s > 0; s >>= 1) {
        if (j < s) red[j] = fmaxf(red[j], red[j + s]);
        __syncthreads();
    }
    float mx2 = red[0];
    if (j == 0) g_mx2 = mx2;

    if (j < M) {
        float cA = -L * g00;
        float cB = -L * g11;
        float cC = -L * 2.0f * g01;
        float cD =  L * 2.0f * (g00 * m0 + g01 * m1);
        float cE =  L * 2.0f * (g11 * m1 + g01 * m0);
        float cF =  L * (logw - (g00 * m0 * m0 + 2.0f * g01 * m0 * m1 + g11 * m1 * m1))
                    - mx2;

        float* gp = (float*)g_coef;
        int p = j >> 1, h = j & 1;
        int base = p * 12 + h * 6;
        gp[base + 0] = cA;
        gp[base + 1] = cB;
        gp[base + 2] = cC;
        gp[base + 3] = cD;
        gp[base + 4] = cE;
        gp[base + 5] = cF;
    }
}

__device__ __forceinline__ float ex2f(float x) {
    float r;
    asm("ex2.approx.ftz.f32 %0, %1;" : "=f"(r) : "f"(x));
    return r;
}

__device__ __forceinline__ float qeval(float cA, float cB, float cC,
                                       float cD, float cE, float cF,
                                       float x0, float x1,
                                       float x00, float x11, float x01) {
    float t = fmaf(cE, x1, cF);
    t = fmaf(cD, x0,  t);
    t = fmaf(cC, x01, t);
    t = fmaf(cB, x11, t);
    t = fmaf(cA, x00, t);
    return t;
}

// ---------------------------------------------------------------------------
// Main kernel: 512 threads/CTA, 128 CTAs (one per SM, single wave, 4 warps
// per SMSP). S=4 samples per thread-slot; the CTA's four 128-thread quarters
// each cover a quarter of the cluster pairs over the SAME 512 samples;
// partial sums combined through shared memory.
// ---------------------------------------------------------------------------
#define S 4
__global__ __launch_bounds__(512) void gmm_ll_kernel(
    const float* __restrict__ sample,
    float* __restrict__ out,
    int N, int M) {
    __shared__ __align__(16) float4 sc[NPAIR * 3];     // 24 KB
    __shared__ __align__(16) float4 s_part[3 * 128];   // 6 KB partial sums

    const int npair = M >> 1;
    for (int k = threadIdx.x; k < npair * 3; k += blockDim.x)
        sc[k] = g_coef[k];
    __syncthreads();

    const int quarter = threadIdx.x >> 7;     // 0..3: which quarter of clusters
    const int lane = threadIdx.x & 127;       // sample slot within CTA
    const int base = (blockIdx.x * 128 + lane) * S;

    // Load 4 samples (32 B) via two float4 loads (all quarters load the same).
    const float4* sp4 = (const float4*)(sample + 2 * base);
    float4 sA = sp4[0];
    float4 sB = sp4[1];

    float x0[S]  = { sA.x, sA.z, sB.x, sB.z };
    float x1[S]  = { sA.y, sA.w, sB.y, sB.w };
    float x00[S], x11[S], x01[S];
    #pragma unroll
    for (int s = 0; s < S; s++) {
        x00[s] = x0[s] * x0[s];
        x11[s] = x1[s] * x1[s];
        x01[s] = x0[s] * x1[s];
    }

    float acc0[S], acc1[S];
    #pragma unroll
    for (int s = 0; s < S; s++) { acc0[s] = 0.0f; acc1[s] = 0.0f; }

    const int q_np = npair >> 2;              // 128 pairs per quarter
    const float4* cp = sc + 3 * quarter * q_np;

    #pragma unroll 2
    for (int p = 0; p < q_np; p++) {
        float4 v0 = cp[3 * p + 0];  // A0 B0 C0 D0
        float4 v1 = cp[3 * p + 1];  // E0 F0 A1 B1
        float4 v2 = cp[3 * p + 2];  // C1 D1 E1 F1

        #pragma unroll
        for (int s = 0; s < S; s++) {
            float t0 = qeval(v0.x, v0.y, v0.z, v0.w, v1.x, v1.y,
                             x0[s], x1[s], x00[s], x11[s], x01[s]);
            float t1 = qeval(v1.z, v1.w, v2.x, v2.y, v2.z, v2.w,
                             x0[s], x1[s], x00[s], x11[s], x01[s]);
            acc0[s] += ex2f(t0);
            acc1[s] += ex2f(t1);
        }
    }

    float4 mysum;
    mysum.x = acc0[0] + acc1[0];
    mysum.y = acc0[1] + acc1[1];
    mysum.z = acc0[2] + acc1[2];
    mysum.w = acc0[3] + acc1[3];

    if (quarter != 0) s_part[(quarter - 1) * 128 + lane] = mysum;
    __syncthreads();

    if (quarter == 0) {
        float4 p1 = s_part[0 * 128 + lane];
        float4 p2 = s_part[1 * 128 + lane];
        float4 p3 = s_part[2 * 128 + lane];
        float mx2 = g_mx2;
        const float LN2 = 0.6931471805599453f;
        float4 res;
        res.x = (mx2 + __log2f((mysum.x + p1.x) + (p2.x + p3.x))) * LN2;
        res.y = (mx2 + __log2f((mysum.y + p1.y) + (p2.y + p3.y))) * LN2;
        res.z = (mx2 + __log2f((mysum.z + p1.z) + (p2.z + p3.z))) * LN2;
        res.w = (mx2 + __log2f((mysum.w + p1.w) + (p2.w + p3.w))) * LN2;
        *(float4*)(out + base) = res;
    }
}

// ---------------------------------------------------------------------------
// Inputs (metadata order): sample [N,2] f32, mu [M,2] f32, A [M,2,2] f32,
// w [M,1] f32. Output: [N,1] f32.
// ---------------------------------------------------------------------------
extern "C" void kernel_launch(void* const* d_in, const int* in_sizes, int n_in,
                              void* d_out, int out_size) {
    const float* sample = (const float*)d_in[0];
    const float* mu     = (const float*)d_in[1];
    const float* A      = (const float*)d_in[2];
    const float* w      = (const float*)d_in[3];
    float* out = (float*)d_out;

    int N = in_sizes[0] / 2;
    int M = in_sizes[3];

    gmm_prep_kernel<<<1, 1024>>>(mu, A, w, M);

    int samples_per_cta = 128 * S;                             // 512
    int blocks = (N + samples_per_cta - 1) / samples_per_cta;  // 128
    gmm_ll_kernel<<<blocks, 512>>>(sample, out, N, M);
}

// round 10
// speedup vs baseline: 1.4946x; 1.1356x over previous
#include <cuda_runtime.h>
#include <math_constants.h>

// Per-cluster expanded quadratic in log2 domain, shifted by the global max:
//   t2_j(x) = F_j + A_j*x0^2 + B_j*x1^2 + C_j*x0*x1 + D_j*x0 + E_j*x1
// Coeffs absorb log2(e); F absorbs -mx2.
// PAIR-INTERLEAVED packing, 12 floats per pair p (clusters 2p, 2p+1):
//   [A0,A1, B0,B1, C0,C1, D0,D1, E0,E1, F0,F1]
// so each 8-byte word is a ready-made f32x2 operand.
#define MAX_M 1024
#define NPAIR (MAX_M / 2)
__device__ __align__(16) float4 g_coef[NPAIR * 3];  // 24 KB
__device__ float g_mx2;

// ---------------------------------------------------------------------------
// f32x2 packed helpers (sm_100a)
// ---------------------------------------------------------------------------
__device__ __forceinline__ unsigned long long fma2(unsigned long long a,
                                                   unsigned long long b,
                                                   unsigned long long c) {
    unsigned long long d;
    asm("fma.rn.f32x2 %0, %1, %2, %3;" : "=l"(d) : "l"(a), "l"(b), "l"(c));
    return d;
}
__device__ __forceinline__ unsigned long long pack2(float lo, float hi) {
    unsigned long long d;
    asm("mov.b64 %0, {%1, %2};" : "=l"(d) : "f"(lo), "f"(hi));
    return d;
}
__device__ __forceinline__ void unpack2(unsigned long long v, float& lo, float& hi) {
    asm("mov.b64 {%0, %1}, %2;" : "=f"(lo), "=f"(hi) : "l"(v));
}
__device__ __forceinline__ float ex2f(float x) {
    float r;
    asm("ex2.approx.ftz.f32 %0, %1;" : "=f"(r) : "f"(x));
    return r;
}

// ---------------------------------------------------------------------------
// Prep kernel: one block of 1024 threads.
// ---------------------------------------------------------------------------
__global__ void gmm_prep_kernel(const float* __restrict__ mu,
                                const float* __restrict__ A,
                                const float* __restrict__ w,
                                int M) {
    __shared__ float red[1024];
    int j = threadIdx.x;

    float wj = (j < M) ? w[j] : -CUDART_INF_F;

    red[j] = wj;
    __syncthreads();
    for (int s = 512; s > 0; s >>= 1) {
        if (j < s) red[j] = fmaxf(red[j], red[j + s]);
        __syncthreads();
    }
    float wmax = red[0];
    __syncthreads();

    red[j] = (j < M) ? __expf(wj - wmax) : 0.0f;
    __syncthreads();
    for (int s = 512; s > 0; s >>= 1) {
        if (j < s) red[j] += red[j + s];
        __syncthreads();
    }
    float lse_w = wmax + __logf(red[0]);
    __syncthreads();

    float g00 = 0.f, g01 = 0.f, g11 = 0.f, logw = -CUDART_INF_F;
    float m0 = 0.f, m1 = 0.f;
    if (j < M) {
        float a00 = A[j * 4 + 0];
        float a01 = A[j * 4 + 1];
        float a10 = A[j * 4 + 2];
        float a11 = A[j * 4 + 3];
        g00 = 0.5f * (a00 * a00 + a01 * a01);
        g01 = 0.5f * (a00 * a10 + a01 * a11);
        g11 = 0.5f * (a10 * a10 + a11 * a11);
        float det = g00 * g11 - g01 * g01;
        logw = (wj - lse_w) + 0.5f * __logf(det);
        m0 = mu[j * 2 + 0];
        m1 = mu[j * 2 + 1];
    }

    const float L = 1.4426950408889634f;  // log2(e)
    red[j] = L * logw;
    __syncthreads();
    for (int s = 512; s > 0; s >>= 1) {
        if (j < s) red[j] = fmaxf(red[j], red[j + s]);
        __syncthreads();
    }
    float mx2 = red[0];
    if (j == 0) g_mx2 = mx2;

    if (j < M) {
        float cA = -L * g00;
        float cB = -L * g11;
        float cC = -L * 2.0f * g01;
        float cD =  L * 2.0f * (g00 * m0 + g01 * m1);
        float cE =  L * 2.0f * (g11 * m1 + g01 * m0);
        float cF =  L * (logw - (g00 * m0 * m0 + 2.0f * g01 * m0 * m1 + g11 * m1 * m1))
                    - mx2;

        float* gp = (float*)g_coef;
        int p = j >> 1, h = j & 1;
        int base = p * 12;
        gp[base + 0 + h]  = cA;
        gp[base + 2 + h]  = cB;
        gp[base + 4 + h]  = cC;
        gp[base + 6 + h]  = cD;
        gp[base + 8 + h]  = cE;
        gp[base + 10 + h] = cF;
    }
}

// ---------------------------------------------------------------------------
// Main kernel: 512 threads/CTA, 128 CTAs (one per SM, single wave, 4 warps
// per SMSP). S=4 samples per thread-slot; four 128-thread quarters each cover
// a quarter of the cluster pairs over the SAME 512 samples; partial sums
// merged through shared memory. Both clusters of a pair evaluated with ONE
// packed 5x fma.rn.f32x2 chain -> fma-pipe ops per pair-sample drop 12 -> 7.
// ---------------------------------------------------------------------------
#define S 4
__global__ __launch_bounds__(512) void gmm_ll_kernel(
    const float* __restrict__ sample,
    float* __restrict__ out,
    int N, int M) {
    __shared__ __align__(16) float4 sc[NPAIR * 3];     // 24 KB
    __shared__ __align__(16) float4 s_part[3 * 128];   // 6 KB partial sums

    const int npair = M >> 1;
    for (int k = threadIdx.x; k < npair * 3; k += blockDim.x)
        sc[k] = g_coef[k];
    __syncthreads();

    const int quarter = threadIdx.x >> 7;     // 0..3: which quarter of clusters
    const int lane = threadIdx.x & 127;       // sample slot within CTA
    const int base = (blockIdx.x * 128 + lane) * S;

    const float4* sp4 = (const float4*)(sample + 2 * base);
    float4 sA = sp4[0];
    float4 sB = sp4[1];

    float x0[S]  = { sA.x, sA.z, sB.x, sB.z };
    float x1[S]  = { sA.y, sA.w, sB.y, sB.w };

    unsigned long long X00[S], X11[S], X01[S], X0[S], X1[S];
    #pragma unroll
    for (int s = 0; s < S; s++) {
        float x00 = x0[s] * x0[s];
        float x11 = x1[s] * x1[s];
        float x01 = x0[s] * x1[s];
        X00[s] = pack2(x00, x00);
        X11[s] = pack2(x11, x11);
        X01[s] = pack2(x01, x01);
        X0[s]  = pack2(x0[s], x0[s]);
        X1[s]  = pack2(x1[s], x1[s]);
    }

    float acc0[S], acc1[S];
    #pragma unroll
    for (int s = 0; s < S; s++) { acc0[s] = 0.0f; acc1[s] = 0.0f; }

    const int q_np = npair >> 2;              // 128 pairs per quarter
    // 3 x 16B per pair: [A01,B01] [C01,D01] [E01,F01]
    const ulonglong2* cq = (const ulonglong2*)sc + 3 * quarter * q_np;

    #pragma unroll 2
    for (int p = 0; p < q_np; p++) {
        ulonglong2 ab = cq[3 * p + 0];   // .x = A01, .y = B01
        ulonglong2 cd = cq[3 * p + 1];   // .x = C01, .y = D01
        ulonglong2 ef = cq[3 * p + 2];   // .x = E01, .y = F01

        #pragma unroll
        for (int s = 0; s < S; s++) {
            unsigned long long t = fma2(ef.x, X1[s], ef.y);  // E*x1 + F
            t = fma2(cd.y, X0[s],  t);                       // +D*x0
            t = fma2(cd.x, X01[s], t);                       // +C*x0x1
            t = fma2(ab.y, X11[s], t);                       // +B*x1^2
            t = fma2(ab.x, X00[s], t);                       // +A*x0^2
            float tl, th;
            unpack2(t, tl, th);
            acc0[s] += ex2f(tl);
            acc1[s] += ex2f(th);
        }
    }

    float4 mysum;
    mysum.x = acc0[0] + acc1[0];
    mysum.y = acc0[1] + acc1[1];
    mysum.z = acc0[2] + acc1[2];
    mysum.w = acc0[3] + acc1[3];

    if (quarter != 0) s_part[(quarter - 1) * 128 + lane] = mysum;
    __syncthreads();

    if (quarter == 0) {
        float4 p1 = s_part[0 * 128 + lane];
        float4 p2 = s_part[1 * 128 + lane];
        float4 p3 = s_part[2 * 128 + lane];
        float mx2 = g_mx2;
        const float LN2 = 0.6931471805599453f;
        float4 res;
        res.x = (mx2 + __log2f((mysum.x + p1.x) + (p2.x + p3.x))) * LN2;
        res.y = (mx2 + __log2f((mysum.y + p1.y) + (p2.y + p3.y))) * LN2;
        res.z = (mx2 + __log2f((mysum.z + p1.z) + (p2.z + p3.z))) * LN2;
        res.w = (mx2 + __log2f((mysum.w + p1.w) + (p2.w + p3.w))) * LN2;
        *(float4*)(out + base) = res;
    }
}

// ---------------------------------------------------------------------------
// Inputs (metadata order): sample [N,2] f32, mu [M,2] f32, A [M,2,2] f32,
// w [M,1] f32. Output: [N,1] f32.
// ---------------------------------------------------------------------------
extern "C" void kernel_launch(void* const* d_in, const int* in_sizes, int n_in,
                              void* d_out, int out_size) {
    const float* sample = (const float*)d_in[0];
    const float* mu     = (const float*)d_in[1];
    const float* A      = (const float*)d_in[2];
    const float* w      = (const float*)d_in[3];
    float* out = (float*)d_out;

    int N = in_sizes[0] / 2;
    int M = in_sizes[3];

    gmm_prep_kernel<<<1, 1024>>>(mu, A, w, M);

    int samples_per_cta = 128 * S;                             // 512
    int blocks = (N + samples_per_cta - 1) / samples_per_cta;  // 128
    gmm_ll_kernel<<<blocks, 512>>>(sample, out, N, M);
}

// round 14
// speedup vs baseline: 1.7060x; 1.1414x over previous
#include <cuda_runtime.h>
#include <math_constants.h>

// Fully fused GMM log-likelihood.
// Cholesky form per cluster j (log2 domain, global-max shifted), gamma = L L^T:
//   q = || L^T (x - mu) ||^2, so with U = L^T (upper):
//   y0 = c00*x0 + c10*x1 + b0      (c00=sqrt(L)*l00, c10=sqrt(L)*l10)
//   y1 = c11*x1 + b1               (c11=sqrt(L)*l11)
//   u  = y0^2 + y1^2 + NF          (NF = mx2 - L*logw_j >= 0)
//   contribution = exp2(-u)
// Pair-interleaved packed layout, 12 floats per pair p (clusters 2p,2p+1):
//   [c00_0,c00_1, c10_0,c10_1, c11_0,c11_1, b0_0,b0_1, b1_0,b1_1, NF_0,NF_1]
#define MAX_M 1024
#define NPAIR (MAX_M / 2)

// ---------------------------------------------------------------------------
// Packed f32x2 helpers (sm_100a)
// ---------------------------------------------------------------------------
__device__ __forceinline__ unsigned long long fma2(unsigned long long a,
                                                   unsigned long long b,
                                                   unsigned long long c) {
    unsigned long long d;
    asm("fma.rn.f32x2 %0, %1, %2, %3;" : "=l"(d) : "l"(a), "l"(b), "l"(c));
    return d;
}
__device__ __forceinline__ unsigned long long pack2(float lo, float hi) {
    unsigned long long d;
    asm("mov.b64 %0, {%1, %2};" : "=l"(d) : "f"(lo), "f"(hi));
    return d;
}
__device__ __forceinline__ void unpack2(unsigned long long v, float& lo, float& hi) {
    asm("mov.b64 {%0, %1}, %2;" : "=f"(lo), "=f"(hi) : "l"(v));
}
__device__ __forceinline__ float ex2f(float x) {
    float r;
    asm("ex2.approx.ftz.f32 %0, %1;" : "=f"(r) : "f"(x));
    return r;
}

// ---------------------------------------------------------------------------
// Block reductions over 512 threads (16 warps) via shuffles + small smem.
// ---------------------------------------------------------------------------
__device__ __forceinline__ float block_max(float v, float* red) {
    #pragma unroll
    for (int o = 16; o > 0; o >>= 1)
        v = fmaxf(v, __shfl_down_sync(0xFFFFFFFFu, v, o));
    if ((threadIdx.x & 31) == 0) red[threadIdx.x >> 5] = v;
    __syncthreads();
    if (threadIdx.x < 32) {
        float x = (threadIdx.x < 16) ? red[threadIdx.x] : -CUDART_INF_F;
        #pragma unroll
        for (int o = 8; o > 0; o >>= 1)
            x = fmaxf(x, __shfl_down_sync(0xFFFFFFFFu, x, o));
        if (threadIdx.x == 0) red[16] = x;
    }
    __syncthreads();
    float r = red[16];
    __syncthreads();
    return r;
}

__device__ __forceinline__ float block_sum(float v, float* red) {
    #pragma unroll
    for (int o = 16; o > 0; o >>= 1)
        v += __shfl_down_sync(0xFFFFFFFFu, v, o);
    if ((threadIdx.x & 31) == 0) red[threadIdx.x >> 5] = v;
    __syncthreads();
    if (threadIdx.x < 32) {
        float x = (threadIdx.x < 16) ? red[threadIdx.x] : 0.0f;
        #pragma unroll
        for (int o = 8; o > 0; o >>= 1)
            x += __shfl_down_sync(0xFFFFFFFFu, x, o);
        if (threadIdx.x == 0) red[16] = x;
    }
    __syncthreads();
    float r = red[16];
    __syncthreads();
    return r;
}

// ---------------------------------------------------------------------------
// Fused kernel: 512 threads/CTA, 128 CTAs (one per SM, single wave).
// Phase 1 (prep, every CTA): softmax(w), Cholesky coeffs -> smem.
// Phase 2: 8 groups x 64 lanes; group g covers cluster pairs [64g, 64g+64);
//          lane owns S=8 consecutive samples; partial sums merged via smem.
// ---------------------------------------------------------------------------
#define S 8
__global__ __launch_bounds__(512) void gmm_fused_kernel(
    const float* __restrict__ sample,
    const float* __restrict__ mu,
    const float* __restrict__ A,
    const float* __restrict__ w,
    float* __restrict__ out,
    int N, int M) {
    __shared__ __align__(16) float4 sc[NPAIR * 3];          // 24 KB coeffs
    __shared__ __align__(16) float4 s_part[7 * 64 * 2];     // 14 KB partials
    __shared__ float red[17];

    const int tid = threadIdx.x;
    const float L = 1.4426950408889634f;   // log2(e)
    const float LN2 = 0.6931471805599453f;

    // ---------------- Phase 1: prep (2 clusters per thread) ----------------
    int j0 = tid, j1 = tid + 512;
    float w0 = (j0 < M) ? w[j0] : -CUDART_INF_F;
    float w1 = (j1 < M) ? w[j1] : -CUDART_INF_F;

    float wmax = block_max(fmaxf(w0, w1), red);
    float esum = ((j0 < M) ? __expf(w0 - wmax) : 0.0f)
               + ((j1 < M) ? __expf(w1 - wmax) : 0.0f);
    float lse_w = wmax + __logf(block_sum(esum, red));

    // per-cluster quantities
    float logw[2] = { -CUDART_INF_F, -CUDART_INF_F };
    float c00[2], c10[2], c11[2], m0v[2], m1v[2];
    #pragma unroll
    for (int h = 0; h < 2; h++) {
        int j = (h == 0) ? j0 : j1;
        if (j < M) {
            float a00 = A[j * 4 + 0];
            float a01 = A[j * 4 + 1];
            float a10 = A[j * 4 + 2];
            float a11 = A[j * 4 + 3];
            float g00 = 0.5f * (a00 * a00 + a01 * a01);
            float g01 = 0.5f * (a00 * a10 + a01 * a11);
            float g11 = 0.5f * (a10 * a10 + a11 * a11);
            float det = g00 * g11 - g01 * g01;
            float wj  = (h == 0) ? w0 : w1;
            logw[h] = (wj - lse_w) + 0.5f * __logf(det);
            // Cholesky gamma = L_chol L_chol^T, scaled by sqrt(log2 e).
            // q = ||L_chol^T d||^2: y0 = l00*d0 + l10*d1, y1 = l11*d1.
            float sl  = sqrtf(L);
            float l00 = sqrtf(g00);
            float l10 = g01 / l00;
            float l11 = sqrtf(fmaxf(g11 - l10 * l10, 0.0f));
            c00[h] = sl * l00;
            c10[h] = sl * l10;
            c11[h] = sl * l11;
            m0v[h] = mu[j * 2 + 0];
            m1v[h] = mu[j * 2 + 1];
        }
    }

    float mx2 = block_max(L * fmaxf(logw[0], logw[1]), red);

    float* gp = (float*)sc;
    #pragma unroll
    for (int h = 0; h < 2; h++) {
        int j = (h == 0) ? j0 : j1;
        if (j < M) {
            // y0 = c00*x0 + c10*x1 + b0;  y1 = c11*x1 + b1
            float b0 = -(c00[h] * m0v[h] + c10[h] * m1v[h]);
            float b1 = -(c11[h] * m1v[h]);
            float NF = mx2 - L * logw[h];   // >= 0
            int p = j >> 1, hh = j & 1;
            int base = p * 12;
            gp[base + 0 + hh]  = c00[h];
            gp[base + 2 + hh]  = c10[h];
            gp[base + 4 + hh]  = c11[h];
            gp[base + 6 + hh]  = b0;
            gp[base + 8 + hh]  = b1;
            gp[base + 10 + hh] = NF;
        }
    }
    __syncthreads();

    // ---------------- Phase 2: main loop ----------------
    const int group = tid >> 6;          // 0..7
    const int lane  = tid & 63;          // sample slot
    const int base  = (blockIdx.x * 64 + lane) * S;

    // Load 8 samples = 16 floats = 4 float4
    const float4* sp4 = (const float4*)(sample + 2 * base);
    float4 r0 = sp4[0], r1 = sp4[1], r2 = sp4[2], r3 = sp4[3];
    float x0[S] = { r0.x, r0.z, r1.x, r1.z, r2.x, r2.z, r3.x, r3.z };
    float x1[S] = { r0.y, r0.w, r1.y, r1.w, r2.y, r2.w, r3.y, r3.w };

    unsigned long long X0[S], X1[S];
    #pragma unroll
    for (int s = 0; s < S; s++) {
        X0[s] = pack2(x0[s], x0[s]);
        X1[s] = pack2(x1[s], x1[s]);
    }

    float acc[S];
    #pragma unroll
    for (int s = 0; s < S; s++) acc[s] = 0.0f;

    const int q_np = (M >> 1) >> 3;      // 64 pairs per group
    const ulonglong2* cq = (const ulonglong2*)sc + 3 * group * q_np;
    const unsigned long long SGN = 0x8000000080000000ULL;

    #pragma unroll 2
    for (int p = 0; p < q_np; p++) {
        ulonglong2 q0 = cq[3 * p + 0];   // {c00, c10}
        ulonglong2 q1 = cq[3 * p + 1];   // {c11, b0}
        ulonglong2 q2 = cq[3 * p + 2];   // {b1, NF}

        #pragma unroll
        for (int s = 0; s < S; s++) {
            unsigned long long Y0 = fma2(q0.x, X0[s], fma2(q0.y, X1[s], q1.y));
            unsigned long long Y1 = fma2(q1.x, X1[s], q2.x);
            unsigned long long U  = fma2(Y1, Y1, fma2(Y0, Y0, q2.y));
            unsigned long long NU = U ^ SGN;    // t = -u, both lanes
            float tl, th;
            unpack2(NU, tl, th);
            acc[s] += ex2f(tl);
            acc[s] += ex2f(th);
        }
    }

    float4 sumA = make_float4(acc[0], acc[1], acc[2], acc[3]);
    float4 sumB = make_float4(acc[4], acc[5], acc[6], acc[7]);

    if (group != 0) {
        s_part[((group - 1) * 64 + lane) * 2 + 0] = sumA;
        s_part[((group - 1) * 64 + lane) * 2 + 1] = sumB;
    }
    __syncthreads();

    if (group == 0) {
        #pragma unroll
        for (int g = 0; g < 7; g++) {
            float4 pa = s_part[(g * 64 + lane) * 2 + 0];
            float4 pb = s_part[(g * 64 + lane) * 2 + 1];
            sumA.x += pa.x; sumA.y += pa.y; sumA.z += pa.z; sumA.w += pa.w;
            sumB.x += pb.x; sumB.y += pb.y; sumB.z += pb.z; sumB.w += pb.w;
        }
        float4 oA, oB;
        oA.x = (mx2 + __log2f(sumA.x)) * LN2;
        oA.y = (mx2 + __log2f(sumA.y)) * LN2;
        oA.z = (mx2 + __log2f(sumA.z)) * LN2;
        oA.w = (mx2 + __log2f(sumA.w)) * LN2;
        oB.x = (mx2 + __log2f(sumB.x)) * LN2;
        oB.y = (mx2 + __log2f(sumB.y)) * LN2;
        oB.z = (mx2 + __log2f(sumB.z)) * LN2;
        oB.w = (mx2 + __log2f(sumB.w)) * LN2;
        float4* op = (float4*)(out + base);
        op[0] = oA;
        op[1] = oB;
    }
}

// ---------------------------------------------------------------------------
// Inputs (metadata order): sample [N,2] f32, mu [M,2] f32, A [M,2,2] f32,
// w [M,1] f32. Output: [N,1] f32.
// ---------------------------------------------------------------------------
extern "C" void kernel_launch(void* const* d_in, const int* in_sizes, int n_in,
                              void* d_out, int out_size) {
    const float* sample = (const float*)d_in[0];
    const float* mu     = (const float*)d_in[1];
    const float* A      = (const float*)d_in[2];
    const float* w      = (const float*)d_in[3];
    float* out = (float*)d_out;

    int N = in_sizes[0] / 2;
    int M = in_sizes[3];

    int samples_per_cta = 64 * S;                              // 512
    int blocks = (N + samples_per_cta - 1) / samples_per_cta;  // 128
    gmm_fused_kernel<<<blocks, 512>>>(sample, mu, A, w, out, N, M);
}

// round 15
// speedup vs baseline: 1.7079x; 1.0011x over previous
#include <cuda_runtime.h>
#include <math_constants.h>

// Fully fused GMM log-likelihood.
// Cholesky form per cluster j (log2 domain, global-max shifted), gamma = L L^T:
//   q = || L^T (x - mu) ||^2, so with U = L^T (upper):
//   y0 = c00*x0 + c10*x1 + b0      (c00=sqrt(L)*l00, c10=sqrt(L)*l10)
//   y1 = c11*x1 + b1               (c11=sqrt(L)*l11)
//   u  = y0^2 + y1^2 + NF          (NF = mx2 - L*logw_j >= 0)
//   contribution = exp2(-u)
// Pair-interleaved packed layout, 12 floats per pair p (clusters 2p,2p+1):
//   [c00_0,c00_1, c10_0,c10_1, c11_0,c11_1, b0_0,b0_1, b1_0,b1_1, NF_0,NF_1]
#define MAX_M 1024
#define NPAIR (MAX_M / 2)

// ---------------------------------------------------------------------------
// Packed f32x2 helpers (sm_100a)
// ---------------------------------------------------------------------------
__device__ __forceinline__ unsigned long long fma2(unsigned long long a,
                                                   unsigned long long b,
                                                   unsigned long long c) {
    unsigned long long d;
    asm("fma.rn.f32x2 %0, %1, %2, %3;" : "=l"(d) : "l"(a), "l"(b), "l"(c));
    return d;
}
__device__ __forceinline__ unsigned long long pack2(float lo, float hi) {
    unsigned long long d;
    asm("mov.b64 %0, {%1, %2};" : "=l"(d) : "f"(lo), "f"(hi));
    return d;
}
__device__ __forceinline__ void unpack2(unsigned long long v, float& lo, float& hi) {
    asm("mov.b64 {%0, %1}, %2;" : "=f"(lo), "=f"(hi) : "l"(v));
}
__device__ __forceinline__ float ex2f(float x) {
    float r;
    asm("ex2.approx.ftz.f32 %0, %1;" : "=f"(r) : "f"(x));
    return r;
}

// ---------------------------------------------------------------------------
// Block reductions over 512 threads (16 warps) via shuffles + small smem.
// ---------------------------------------------------------------------------
__device__ __forceinline__ float block_max(float v, float* red) {
    #pragma unroll
    for (int o = 16; o > 0; o >>= 1)
        v = fmaxf(v, __shfl_down_sync(0xFFFFFFFFu, v, o));
    if ((threadIdx.x & 31) == 0) red[threadIdx.x >> 5] = v;
    __syncthreads();
    if (threadIdx.x < 32) {
        float x = (threadIdx.x < 16) ? red[threadIdx.x] : -CUDART_INF_F;
        #pragma unroll
        for (int o = 8; o > 0; o >>= 1)
            x = fmaxf(x, __shfl_down_sync(0xFFFFFFFFu, x, o));
        if (threadIdx.x == 0) red[16] = x;
    }
    __syncthreads();
    float r = red[16];
    __syncthreads();
    return r;
}

__device__ __forceinline__ float block_sum(float v, float* red) {
    #pragma unroll
    for (int o = 16; o > 0; o >>= 1)
        v += __shfl_down_sync(0xFFFFFFFFu, v, o);
    if ((threadIdx.x & 31) == 0) red[threadIdx.x >> 5] = v;
    __syncthreads();
    if (threadIdx.x < 32) {
        float x = (threadIdx.x < 16) ? red[threadIdx.x] : 0.0f;
        #pragma unroll
        for (int o = 8; o > 0; o >>= 1)
            x += __shfl_down_sync(0xFFFFFFFFu, x, o);
        if (threadIdx.x == 0) red[16] = x;
    }
    __syncthreads();
    float r = red[16];
    __syncthreads();
    return r;
}

// ---------------------------------------------------------------------------
// Fused kernel: 512 threads/CTA, 128 CTAs (one per SM, single wave).
// __launch_bounds__(512, 1): unlock up to 128 regs/thread so all 8
// per-sample FMA2->EX2 chains keep private temps (at 64 regs ptxas reuses
// temps across chains, serializing them -> issue stuck ~52%).
// Phase 1 (prep, every CTA): softmax(w), Cholesky coeffs -> smem.
// Phase 2: 8 groups x 64 lanes; group g covers cluster pairs [64g, 64g+64);
//          lane owns S=8 consecutive samples; partial sums merged via smem.
// ---------------------------------------------------------------------------
#define S 8
__global__ __launch_bounds__(512, 1) void gmm_fused_kernel(
    const float* __restrict__ sample,
    const float* __restrict__ mu,
    const float* __restrict__ A,
    const float* __restrict__ w,
    float* __restrict__ out,
    int N, int M) {
    __shared__ __align__(16) float4 sc[NPAIR * 3];          // 24 KB coeffs
    __shared__ __align__(16) float4 s_part[7 * 64 * 2];     // 14 KB partials
    __shared__ float red[17];

    const int tid = threadIdx.x;
    const float L = 1.4426950408889634f;   // log2(e)
    const float LN2 = 0.6931471805599453f;

    // ---------------- Phase 1: prep (2 clusters per thread) ----------------
    int j0 = tid, j1 = tid + 512;
    float w0 = (j0 < M) ? w[j0] : -CUDART_INF_F;
    float w1 = (j1 < M) ? w[j1] : -CUDART_INF_F;

    float wmax = block_max(fmaxf(w0, w1), red);
    float esum = ((j0 < M) ? __expf(w0 - wmax) : 0.0f)
               + ((j1 < M) ? __expf(w1 - wmax) : 0.0f);
    float lse_w = wmax + __logf(block_sum(esum, red));

    // per-cluster quantities
    float logw[2] = { -CUDART_INF_F, -CUDART_INF_F };
    float c00[2], c10[2], c11[2], m0v[2], m1v[2];
    #pragma unroll
    for (int h = 0; h < 2; h++) {
        int j = (h == 0) ? j0 : j1;
        if (j < M) {
            float a00 = A[j * 4 + 0];
            float a01 = A[j * 4 + 1];
            float a10 = A[j * 4 + 2];
            float a11 = A[j * 4 + 3];
            float g00 = 0.5f * (a00 * a00 + a01 * a01);
            float g01 = 0.5f * (a00 * a10 + a01 * a11);
            float g11 = 0.5f * (a10 * a10 + a11 * a11);
            float det = g00 * g11 - g01 * g01;
            float wj  = (h == 0) ? w0 : w1;
            logw[h] = (wj - lse_w) + 0.5f * __logf(det);
            // Cholesky gamma = L_chol L_chol^T, scaled by sqrt(log2 e).
            // q = ||L_chol^T d||^2: y0 = l00*d0 + l10*d1, y1 = l11*d1.
            float sl  = sqrtf(L);
            float l00 = sqrtf(g00);
            float l10 = g01 / l00;
            float l11 = sqrtf(fmaxf(g11 - l10 * l10, 0.0f));
            c00[h] = sl * l00;
            c10[h] = sl * l10;
            c11[h] = sl * l11;
            m0v[h] = mu[j * 2 + 0];
            m1v[h] = mu[j * 2 + 1];
        }
    }

    float mx2 = block_max(L * fmaxf(logw[0], logw[1]), red);

    float* gp = (float*)sc;
    #pragma unroll
    for (int h = 0; h < 2; h++) {
        int j = (h == 0) ? j0 : j1;
        if (j < M) {
            // y0 = c00*x0 + c10*x1 + b0;  y1 = c11*x1 + b1
            float b0 = -(c00[h] * m0v[h] + c10[h] * m1v[h]);
            float b1 = -(c11[h] * m1v[h]);
            float NF = mx2 - L * logw[h];   // >= 0
            int p = j >> 1, hh = j & 1;
            int base = p * 12;
            gp[base + 0 + hh]  = c00[h];
            gp[base + 2 + hh]  = c10[h];
            gp[base + 4 + hh]  = c11[h];
            gp[base + 6 + hh]  = b0;
            gp[base + 8 + hh]  = b1;
            gp[base + 10 + hh] = NF;
        }
    }
    __syncthreads();

    // ---------------- Phase 2: main loop ----------------
    const int group = tid >> 6;          // 0..7
    const int lane  = tid & 63;          // sample slot
    const int base  = (blockIdx.x * 64 + lane) * S;

    // Load 8 samples = 16 floats = 4 float4
    const float4* sp4 = (const float4*)(sample + 2 * base);
    float4 r0 = sp4[0], r1 = sp4[1], r2 = sp4[2], r3 = sp4[3];
    float x0[S] = { r0.x, r0.z, r1.x, r1.z, r2.x, r2.z, r3.x, r3.z };
    float x1[S] = { r0.y, r0.w, r1.y, r1.w, r2.y, r2.w, r3.y, r3.w };

    unsigned long long X0[S], X1[S];
    #pragma unroll
    for (int s = 0; s < S; s++) {
        X0[s] = pack2(x0[s], x0[s]);
        X1[s] = pack2(x1[s], x1[s]);
    }

    float acc[S];
    #pragma unroll
    for (int s = 0; s < S; s++) acc[s] = 0.0f;

    const int q_np = (M >> 1) >> 3;      // 64 pairs per group
    const ulonglong2* cq = (const ulonglong2*)sc + 3 * group * q_np;
    const unsigned long long SGN = 0x8000000080000000ULL;

    #pragma unroll 1
    for (int p = 0; p < q_np; p++) {
        ulonglong2 q0 = cq[3 * p + 0];   // {c00, c10}
        ulonglong2 q1 = cq[3 * p + 1];   // {c11, b0}
        ulonglong2 q2 = cq[3 * p + 2];   // {b1, NF}

        #pragma unroll
        for (int s = 0; s < S; s++) {
            unsigned long long Y0 = fma2(q0.x, X0[s], fma2(q0.y, X1[s], q1.y));
            unsigned long long Y1 = fma2(q1.x, X1[s], q2.x);
            unsigned long long U  = fma2(Y1, Y1, fma2(Y0, Y0, q2.y));
            unsigned long long NU = U ^ SGN;    // t = -u, both lanes
            float tl, th;
            unpack2(NU, tl, th);
            acc[s] += ex2f(tl);
            acc[s] += ex2f(th);
        }
    }

    float4 sumA = make_float4(acc[0], acc[1], acc[2], acc[3]);
    float4 sumB = make_float4(acc[4], acc[5], acc[6], acc[7]);

    if (group != 0) {
        s_part[((group - 1) * 64 + lane) * 2 + 0] = sumA;
        s_part[((group - 1) * 64 + lane) * 2 + 1] = sumB;
    }
    __syncthreads();

    if (group == 0) {
        #pragma unroll
        for (int g = 0; g < 7; g++) {
            float4 pa = s_part[(g * 64 + lane) * 2 + 0];
            float4 pb = s_part[(g * 64 + lane) * 2 + 1];
            sumA.x += pa.x; sumA.y += pa.y; sumA.z += pa.z; sumA.w += pa.w;
            sumB.x += pb.x; sumB.y += pb.y; sumB.z += pb.z; sumB.w += pb.w;
        }
        float4 oA, oB;
        oA.x = (mx2 + __log2f(sumA.x)) * LN2;
        oA.y = (mx2 + __log2f(sumA.y)) * LN2;
        oA.z = (mx2 + __log2f(sumA.z)) * LN2;
        oA.w = (mx2 + __log2f(sumA.w)) * LN2;
        oB.x = (mx2 + __log2f(sumB.x)) * LN2;
        oB.y = (mx2 + __log2f(sumB.y)) * LN2;
        oB.z = (mx2 + __log2f(sumB.z)) * LN2;
        oB.w = (mx2 + __log2f(sumB.w)) * LN2;
        float4* op = (float4*)(out + base);
        op[0] = oA;
        op[1] = oB;
    }
}

// ---------------------------------------------------------------------------
// Inputs (metadata order): sample [N,2] f32, mu [M,2] f32, A [M,2,2] f32,
// w [M,1] f32. Output: [N,1] f32.
// ---------------------------------------------------------------------------
extern "C" void kernel_launch(void* const* d_in, const int* in_sizes, int n_in,
                              void* d_out, int out_size) {
    const float* sample = (const float*)d_in[0];
    const float* mu     = (const float*)d_in[1];
    const float* A      = (const float*)d_in[2];
    const float* w      = (const float*)d_in[3];
    float* out = (float*)d_out;

    int N = in_sizes[0] / 2;
    int M = in_sizes[3];

    int samples_per_cta = 64 * S;                              // 512
    int blocks = (N + samples_per_cta - 1) / samples_per_cta;  // 128
    gmm_fused_kernel<<<blocks, 512>>>(sample, mu, A, w, out, N, M);
}